// round 6
// baseline (speedup 1.0000x reference)
#include <cuda_runtime.h>

// SrbQpCtrl: tau = zeros([2e6,10], f32) = 80 MB constant fill.
// Established (R1-R5): CE memset, SIMT STG.E.128, and TMA bulk-store all cap
// at ~3100 B/cyc — the sm_103a chip-level L2 WRITE-port floor (half the
// 6300 B/cyc read cap). Kernel floor ~12.7 us + ~2 us graph overhead.
// Final micro-variant: exact cover, 1024 float4 per block, 4 block-interleaved
// fully-coalesced STG.E.128 per thread (branch-free for interior blocks).

__global__ void __launch_bounds__(256) zero_fill_exact4(float4* __restrict__ out, int n4) {
    int base = blockIdx.x * 1024 + threadIdx.x;  // block covers [blk*1024, +1024)
    const float4 z = make_float4(0.f, 0.f, 0.f, 0.f);
    if (base + 768 < n4) {                       // interior: branch-free 4x store
        out[base +   0] = z;
        out[base + 256] = z;
        out[base + 512] = z;
        out[base + 768] = z;
    } else {                                     // last block tail
        if (base       < n4) out[base]       = z;
        if (base + 256 < n4) out[base + 256] = z;
        if (base + 512 < n4) out[base + 512] = z;
        // base+768 >= n4 here by construction
    }
}

extern "C" void kernel_launch(void* const* d_in, const int* in_sizes, int n_in,
                              void* d_out, int out_size) {
    (void)d_in; (void)in_sizes; (void)n_in;
    int n4 = out_size / 4;                       // 5,000,000 float4
    int blocks = (n4 + 1023) / 1024;             // 4883 blocks, exact cover
    zero_fill_exact4<<<blocks, 256>>>((float4*)d_out, n4);

    int tail = out_size - n4 * 4;                // 0 for 20M floats; defensive
    if (tail > 0)
        cudaMemsetAsync((float*)d_out + (size_t)n4 * 4, 0, (size_t)tail * sizeof(float), 0);
}

// round 7
// speedup vs baseline: 1.0129x; 1.0129x over previous
#include <cuda_runtime.h>

// SrbQpCtrl: tau = zeros([2e6,10], f32) = 80 MB constant fill (input x unused;
// QP with Q=I, q=0, z>=0 has closed-form optimum z*=0).
//
// FINAL. Established across R1-R6: CE memset, SIMT STG.E.128 (three layouts),
// and TMA bulk S2G all converge at ~3100 B/cyc — the sm_103a chip-level L2
// WRITE-port cap (half the 6300 B/cyc LTS read cap). 80 MB mandatory write
// (d_out is poisoned before timing) / 3100 B/cyc ≈ 12.7 us kernel + ~2 us
// graph-replay overhead = ~14.7 us wall floor. This is the best-measured
// variant (R5): exact cover, 512 float4 per block, two block-interleaved
// fully-coalesced STG.E.128 per thread.

__global__ void __launch_bounds__(256) zero_fill_exact(float4* __restrict__ out, int n4) {
    int base = blockIdx.x * 512 + threadIdx.x;   // block covers [blk*512, blk*512+512)
    const float4 z = make_float4(0.f, 0.f, 0.f, 0.f);
    if (base < n4)        out[base] = z;         // float4 0..255 of the block span
    if (base + 256 < n4)  out[base + 256] = z;   // float4 256..511
}

extern "C" void kernel_launch(void* const* d_in, const int* in_sizes, int n_in,
                              void* d_out, int out_size) {
    (void)d_in; (void)in_sizes; (void)n_in;
    int n4 = out_size / 4;                       // 5,000,000 float4
    int blocks = (n4 + 511) / 512;               // 9766 blocks, exact cover
    zero_fill_exact<<<blocks, 256>>>((float4*)d_out, n4);

    int tail = out_size - n4 * 4;                // 0 for 20M floats; defensive
    if (tail > 0)
        cudaMemsetAsync((float*)d_out + (size_t)n4 * 4, 0, (size_t)tail * sizeof(float), 0);
}